// round 1
// baseline (speedup 1.0000x reference)
#include <cuda_runtime.h>
#include <math.h>

// Problem constants (fixed by setup_inputs)
#define Bb 2
#define Tt 2048
#define Dd 2048
#define NQ 16
#define NK 8
#define HD 128

// Scratch (device globals: allocation-free rule)
__device__ float g_q[(size_t)Bb * Tt * NQ * HD]; // 32 MB
__device__ float g_k[(size_t)Bb * Tt * NK * HD]; // 16 MB
__device__ float g_v[(size_t)Bb * Tt * NK * HD]; // 16 MB
__device__ float g_o[(size_t)Bb * Tt * NQ * HD]; // 32 MB

// ---------------------------------------------------------------------------
// Tiled SGEMM: C[M,N] = A[M,K] @ B[K,N], all row-major, M%128==0, N%128==0, K%16==0
// 256 threads, 128x128 tile, 8x8 per-thread microtile.
// ---------------------------------------------------------------------------
__global__ __launch_bounds__(256) void sgemm128(const float* __restrict__ A,
                                                const float* __restrict__ B,
                                                float* __restrict__ C,
                                                int M, int N, int K) {
    __shared__ float sA[16][132]; // A^T tile, padded
    __shared__ float sB[16][132]; // B tile, padded
    const int tid = threadIdx.x;
    const int bm = blockIdx.y << 7;
    const int bn = blockIdx.x << 7;
    const int tr = (tid >> 4) << 3;
    const int tc = (tid & 15) << 3;

    float acc[8][8];
#pragma unroll
    for (int i = 0; i < 8; i++)
#pragma unroll
        for (int j = 0; j < 8; j++) acc[i][j] = 0.f;

    for (int k0 = 0; k0 < K; k0 += 16) {
#pragma unroll
        for (int u = 0; u < 2; u++) {
            int f = tid + (u << 8);
            int r = f >> 2, c = (f & 3) << 2;
            float4 va = *(const float4*)(A + (size_t)(bm + r) * K + k0 + c);
            sA[c + 0][r] = va.x;
            sA[c + 1][r] = va.y;
            sA[c + 2][r] = va.z;
            sA[c + 3][r] = va.w;
            int rb = f >> 5, cb = (f & 31) << 2;
            *(float4*)&sB[rb][cb] = *(const float4*)(B + (size_t)(k0 + rb) * N + bn + cb);
        }
        __syncthreads();
#pragma unroll
        for (int k = 0; k < 16; k++) {
            float4 a0 = *(const float4*)&sA[k][tr];
            float4 a1 = *(const float4*)&sA[k][tr + 4];
            float4 b0 = *(const float4*)&sB[k][tc];
            float4 b1 = *(const float4*)&sB[k][tc + 4];
            float a[8] = {a0.x, a0.y, a0.z, a0.w, a1.x, a1.y, a1.z, a1.w};
            float bv[8] = {b0.x, b0.y, b0.z, b0.w, b1.x, b1.y, b1.z, b1.w};
#pragma unroll
            for (int i = 0; i < 8; i++)
#pragma unroll
                for (int j = 0; j < 8; j++)
                    acc[i][j] = fmaf(a[i], bv[j], acc[i][j]);
        }
        __syncthreads();
    }

#pragma unroll
    for (int i = 0; i < 8; i++) {
        float* cp = C + (size_t)(bm + tr + i) * N + bn + tc;
        *(float4*)cp = make_float4(acc[i][0], acc[i][1], acc[i][2], acc[i][3]);
        *(float4*)(cp + 4) = make_float4(acc[i][4], acc[i][5], acc[i][6], acc[i][7]);
    }
}

// ---------------------------------------------------------------------------
// Fused RMSNorm + RoPE, in place on a (rows, heads, HD) buffer.
// One block (128 threads) per (row, head). pos = t (cur_ind=0, no left pad).
// ---------------------------------------------------------------------------
__global__ __launch_bounds__(128) void rms_rope(float* __restrict__ buf,
                                                const float* __restrict__ w,
                                                int heads) {
    const int idx = blockIdx.x;
    const int t = (idx / heads) % Tt;
    float* p = buf + (size_t)idx * HD;
    const int h = threadIdx.x;

    float x = p[h];
    float ss = x * x;
#pragma unroll
    for (int off = 16; off; off >>= 1) ss += __shfl_xor_sync(0xffffffffu, ss, off);
    __shared__ float red[4];
    __shared__ float sy[HD];
    if ((h & 31) == 0) red[h >> 5] = ss;
    __syncthreads();
    float tot = red[0] + red[1] + red[2] + red[3];
    float rinv = rsqrtf(tot * (1.0f / (float)HD) + 1e-6f);
    float y = w[h] * x * rinv;
    sy[h] = y;
    __syncthreads();

    // RoPE: inv_freq_i = theta^(-i/64), i = h mod 64; angle = t * inv_freq
    int i = h & 63;
    double ang = (double)t * exp(-0.21586735246819178 * (double)i); // ln(1e6)/64
    double sd, cd;
    sincos(ang, &sd, &cd);
    float s = (float)sd, c = (float)cd;
    float out;
    if (h < 64) out = y * c - sy[h + 64] * s;
    else        out = y * c + sy[h - 64] * s;
    p[h] = out;
}

// ---------------------------------------------------------------------------
// Flash attention, fp32, causal. Tile 64 (M) x 64 (N), H=128.
// Grid: (T/64, NQ, B). 256 threads.
// Thread (r0 = (tid>>4)*4 rows, c1 = tid&15): S cols {c1+16j}, O cols [8*c1, 8*c1+8)
// ---------------------------------------------------------------------------
#define KSTR 132
__global__ __launch_bounds__(256) void flash_attn(const float* __restrict__ Q,
                                                  const float* __restrict__ Kc,
                                                  const float* __restrict__ Vc,
                                                  float* __restrict__ O) {
    extern __shared__ float sm[];
    float* sQ = sm;                   // 64 x KSTR
    float* sK = sm + 64 * KSTR;       // 64 x KSTR
    float* sV = sm + 2 * 64 * KSTR;   // 64 x HD
    float* sP = sV + 64 * HD;         // 64 x 64

    const int tid = threadIdx.x;
    const int b = blockIdx.z, n = blockIdx.y;
    const int qt = blockIdx.x << 6;
    const int kh = n >> 1; // G = NQ/NK = 2

    // Load Q tile (rows qt..qt+63, head n)
    {
        const float* Qb = Q + (((size_t)(b * Tt + qt)) * NQ + n) * HD;
#pragma unroll
        for (int u = 0; u < 8; u++) {
            int f = tid + (u << 8);
            int r = f >> 5, c = (f & 31) << 2;
            *(float4*)&sQ[r * KSTR + c] = *(const float4*)(Qb + (size_t)r * (NQ * HD) + c);
        }
    }

    const int r0 = (tid >> 4) << 2;
    const int c1 = tid & 15;
    const int oc = c1 << 3;

    float mprev[4], lsum[4], oacc[4][8];
#pragma unroll
    for (int i = 0; i < 4; i++) {
        mprev[i] = -1e30f;
        lsum[i] = 0.f;
#pragma unroll
        for (int j = 0; j < 8; j++) oacc[i][j] = 0.f;
    }

    const float scale = 0.08838834764831845f; // 1/sqrt(128)
    const int ntile = (qt >> 6) + 1;

    for (int st = 0; st < ntile; st++) {
        const int s0 = st << 6;
        __syncthreads(); // protect sK/sV/sP from previous iteration readers
        {
            const float* Kb = Kc + (((size_t)(b * Tt + s0)) * NK + kh) * HD;
            const float* Vb = Vc + (((size_t)(b * Tt + s0)) * NK + kh) * HD;
#pragma unroll
            for (int u = 0; u < 8; u++) {
                int f = tid + (u << 8);
                int r = f >> 5, c = (f & 31) << 2;
                *(float4*)&sK[r * KSTR + c] = *(const float4*)(Kb + (size_t)r * (NK * HD) + c);
                *(float4*)&sV[r * HD + c]  = *(const float4*)(Vb + (size_t)r * (NK * HD) + c);
            }
        }
        __syncthreads();

        // S = Q @ K^T (4x4 microtile, cols interleaved by 16)
        float sacc[4][4];
#pragma unroll
        for (int i = 0; i < 4; i++)
#pragma unroll
            for (int j = 0; j < 4; j++) sacc[i][j] = 0.f;

#pragma unroll 4
        for (int k = 0; k < HD; k += 4) {
            float4 qv[4], kv[4];
#pragma unroll
            for (int i = 0; i < 4; i++) qv[i] = *(const float4*)&sQ[(r0 + i) * KSTR + k];
#pragma unroll
            for (int j = 0; j < 4; j++) kv[j] = *(const float4*)&sK[(c1 + (j << 4)) * KSTR + k];
#pragma unroll
            for (int i = 0; i < 4; i++)
#pragma unroll
                for (int j = 0; j < 4; j++) {
                    sacc[i][j] = fmaf(qv[i].x, kv[j].x, sacc[i][j]);
                    sacc[i][j] = fmaf(qv[i].y, kv[j].y, sacc[i][j]);
                    sacc[i][j] = fmaf(qv[i].z, kv[j].z, sacc[i][j]);
                    sacc[i][j] = fmaf(qv[i].w, kv[j].w, sacc[i][j]);
                }
        }

        const bool diag = (s0 == qt);
#pragma unroll
        for (int i = 0; i < 4; i++) {
            const int qrow = qt + r0 + i;
            float mx = -1e30f;
#pragma unroll
            for (int j = 0; j < 4; j++) {
                float v = sacc[i][j] * scale;
                if (diag && (s0 + c1 + (j << 4)) > qrow) v = -1e30f;
                sacc[i][j] = v;
                mx = fmaxf(mx, v);
            }
#pragma unroll
            for (int off = 1; off < 16; off <<= 1)
                mx = fmaxf(mx, __shfl_xor_sync(0xffffffffu, mx, off));
            float mnew = fmaxf(mprev[i], mx);
            float alpha = __expf(mprev[i] - mnew);
            mprev[i] = mnew;
            float psum = 0.f;
#pragma unroll
            for (int j = 0; j < 4; j++) {
                float pv = __expf(sacc[i][j] - mnew);
                sP[(r0 + i) * 64 + c1 + (j << 4)] = pv;
                psum += pv;
            }
#pragma unroll
            for (int off = 1; off < 16; off <<= 1)
                psum += __shfl_xor_sync(0xffffffffu, psum, off);
            lsum[i] = lsum[i] * alpha + psum;
#pragma unroll
            for (int j = 0; j < 8; j++) oacc[i][j] *= alpha;
        }
        __syncwarp(); // sP rows for this thread written only by its own half-warp

        // O += P @ V
#pragma unroll 2
        for (int s = 0; s < 64; s++) {
            float4 v0 = *(const float4*)&sV[s * HD + oc];
            float4 v1 = *(const float4*)&sV[s * HD + oc + 4];
#pragma unroll
            for (int i = 0; i < 4; i++) {
                float pv = sP[(r0 + i) * 64 + s];
                oacc[i][0] = fmaf(pv, v0.x, oacc[i][0]);
                oacc[i][1] = fmaf(pv, v0.y, oacc[i][1]);
                oacc[i][2] = fmaf(pv, v0.z, oacc[i][2]);
                oacc[i][3] = fmaf(pv, v0.w, oacc[i][3]);
                oacc[i][4] = fmaf(pv, v1.x, oacc[i][4]);
                oacc[i][5] = fmaf(pv, v1.y, oacc[i][5]);
                oacc[i][6] = fmaf(pv, v1.z, oacc[i][6]);
                oacc[i][7] = fmaf(pv, v1.w, oacc[i][7]);
            }
        }
    }

#pragma unroll
    for (int i = 0; i < 4; i++) {
        float inv = 1.0f / lsum[i];
        float* Ob = O + (((size_t)(b * Tt + qt + r0 + i)) * NQ + n) * HD + oc;
        *(float4*)Ob = make_float4(oacc[i][0] * inv, oacc[i][1] * inv,
                                   oacc[i][2] * inv, oacc[i][3] * inv);
        *(float4*)(Ob + 4) = make_float4(oacc[i][4] * inv, oacc[i][5] * inv,
                                         oacc[i][6] * inv, oacc[i][7] * inv);
    }
}

// ---------------------------------------------------------------------------
// Launch
// ---------------------------------------------------------------------------
extern "C" void kernel_launch(void* const* d_in, const int* in_sizes, int n_in,
                              void* d_out, int out_size) {
    (void)in_sizes; (void)n_in; (void)out_size;
    const float* x   = (const float*)d_in[0];
    const float* qw  = (const float*)d_in[1];
    const float* kw  = (const float*)d_in[2];
    const float* vw  = (const float*)d_in[3];
    const float* ow  = (const float*)d_in[4];
    const float* qnw = (const float*)d_in[5];
    const float* knw = (const float*)d_in[6];
    float* out = (float*)d_out;

    float *gq, *gk, *gv, *go;
    cudaGetSymbolAddress((void**)&gq, g_q);
    cudaGetSymbolAddress((void**)&gk, g_k);
    cudaGetSymbolAddress((void**)&gv, g_v);
    cudaGetSymbolAddress((void**)&go, g_o);

    const int M = Bb * Tt; // 4096

    // QKV projections
    sgemm128<<<dim3((NQ * HD) / 128, M / 128), 256>>>(x, qw, gq, M, NQ * HD, Dd);
    sgemm128<<<dim3((NK * HD) / 128, M / 128), 256>>>(x, kw, gk, M, NK * HD, Dd);
    sgemm128<<<dim3((NK * HD) / 128, M / 128), 256>>>(x, vw, gv, M, NK * HD, Dd);

    // RMSNorm + RoPE (in place)
    rms_rope<<<M * NQ, 128>>>(gq, qnw, NQ);
    rms_rope<<<M * NK, 128>>>(gk, knw, NK);

    // Flash attention
    size_t smem = (size_t)(2 * 64 * KSTR + 64 * HD + 64 * 64) * sizeof(float); // 116736 B
    cudaFuncSetAttribute(flash_attn, cudaFuncAttributeMaxDynamicSharedMemorySize, (int)smem);
    flash_attn<<<dim3(Tt / 64, NQ, Bb), 256, smem>>>(gq, gk, gv, go);

    // Output projection
    sgemm128<<<dim3(Dd / 128, M / 128), 256>>>(go, ow, out, M, Dd, NQ * HD);
}

// round 2
// speedup vs baseline: 1.8464x; 1.8464x over previous
#include <cuda_runtime.h>
#include <math.h>
#include <stdint.h>

// Problem constants (fixed by setup_inputs)
#define Bb 2
#define Tt 2048
#define Dd 2048
#define NQ 16
#define NK 8
#define HD 128

// Scratch (device globals: allocation-free rule)
__device__ float g_q[(size_t)Bb * Tt * NQ * HD]; // 32 MB
__device__ float g_k[(size_t)Bb * Tt * NK * HD]; // 16 MB
__device__ float g_v[(size_t)Bb * Tt * NK * HD]; // 16 MB
__device__ float g_o[(size_t)Bb * Tt * NQ * HD]; // 32 MB
__device__ float g_sin[Tt * 64];
__device__ float g_cos[Tt * 64];

// ---------------------------------------------------------------------------
// tf32 round helper
// ---------------------------------------------------------------------------
__device__ __forceinline__ float to_tf32(float x) {
    uint32_t r;
    asm("cvt.rna.tf32.f32 %0, %1;" : "=r"(r) : "f"(x));
    return __uint_as_float(r);
}

__device__ __forceinline__ void mma_tf32(float& d0, float& d1, float& d2, float& d3,
                                         uint32_t a0, uint32_t a1, uint32_t a2, uint32_t a3,
                                         uint32_t b0, uint32_t b1) {
    asm volatile(
        "mma.sync.aligned.m16n8k8.row.col.f32.tf32.tf32.f32 "
        "{%0,%1,%2,%3}, {%4,%5,%6,%7}, {%8,%9}, {%0,%1,%2,%3};"
        : "+f"(d0), "+f"(d1), "+f"(d2), "+f"(d3)
        : "r"(a0), "r"(a1), "r"(a2), "r"(a3), "r"(b0), "r"(b1));
}

// ---------------------------------------------------------------------------
// tf32 tensor-core GEMM: C[M,N] = A[M,K] @ B[K,N], row-major fp32 in/out.
// 256 threads, block tile 128x128x16, 8 warps in 2x4 grid, warp tile 64x32.
// ---------------------------------------------------------------------------
__global__ __launch_bounds__(256) void gemm_tf32(const float* __restrict__ A,
                                                 const float* __restrict__ B,
                                                 float* __restrict__ C,
                                                 int M, int N, int K) {
    __shared__ float sA[16][132]; // [k][m], tf32-rounded
    __shared__ float sB[16][132]; // [k][n], tf32-rounded
    const int tid = threadIdx.x;
    const int bm = blockIdx.y << 7;
    const int bn = blockIdx.x << 7;
    const int warp = tid >> 5, lane = tid & 31;
    const int wm = (warp >> 2) << 6;  // 0 or 64
    const int wn = (warp & 3) << 5;   // 0,32,64,96
    const int grp = lane >> 2, qd = lane & 3;

    float acc[4][4][4];
#pragma unroll
    for (int i = 0; i < 4; i++)
#pragma unroll
        for (int j = 0; j < 4; j++)
#pragma unroll
            for (int r = 0; r < 4; r++) acc[i][j][r] = 0.f;

    for (int k0 = 0; k0 < K; k0 += 16) {
#pragma unroll
        for (int u = 0; u < 2; u++) {
            int f = tid + (u << 8);
            int r = f >> 2, c = (f & 3) << 2;
            float4 va = *(const float4*)(A + (size_t)(bm + r) * K + k0 + c);
            sA[c + 0][r] = to_tf32(va.x);
            sA[c + 1][r] = to_tf32(va.y);
            sA[c + 2][r] = to_tf32(va.z);
            sA[c + 3][r] = to_tf32(va.w);
            int rb = f >> 5, cb = (f & 31) << 2;
            float4 vb = *(const float4*)(B + (size_t)(k0 + rb) * N + bn + cb);
            sB[rb][cb + 0] = to_tf32(vb.x);
            sB[rb][cb + 1] = to_tf32(vb.y);
            sB[rb][cb + 2] = to_tf32(vb.z);
            sB[rb][cb + 3] = to_tf32(vb.w);
        }
        __syncthreads();

#pragma unroll
        for (int ks = 0; ks < 16; ks += 8) {
            uint32_t af[4][4];
#pragma unroll
            for (int mt = 0; mt < 4; mt++) {
                int mrow = wm + (mt << 4);
                af[mt][0] = __float_as_uint(sA[ks + qd][mrow + grp]);
                af[mt][1] = __float_as_uint(sA[ks + qd][mrow + grp + 8]);
                af[mt][2] = __float_as_uint(sA[ks + qd + 4][mrow + grp]);
                af[mt][3] = __float_as_uint(sA[ks + qd + 4][mrow + grp + 8]);
            }
            uint32_t bf[4][2];
#pragma unroll
            for (int nt = 0; nt < 4; nt++) {
                int ncol = wn + (nt << 3) + grp;
                bf[nt][0] = __float_as_uint(sB[ks + qd][ncol]);
                bf[nt][1] = __float_as_uint(sB[ks + qd + 4][ncol]);
            }
#pragma unroll
            for (int mt = 0; mt < 4; mt++)
#pragma unroll
                for (int nt = 0; nt < 4; nt++)
                    mma_tf32(acc[mt][nt][0], acc[mt][nt][1], acc[mt][nt][2], acc[mt][nt][3],
                             af[mt][0], af[mt][1], af[mt][2], af[mt][3],
                             bf[nt][0], bf[nt][1]);
        }
        __syncthreads();
    }

#pragma unroll
    for (int mt = 0; mt < 4; mt++) {
#pragma unroll
        for (int nt = 0; nt < 4; nt++) {
            int row = bm + wm + (mt << 4) + grp;
            int col = bn + wn + (nt << 3) + (qd << 1);
            *(float2*)(C + (size_t)row * N + col) =
                make_float2(acc[mt][nt][0], acc[mt][nt][1]);
            *(float2*)(C + (size_t)(row + 8) * N + col) =
                make_float2(acc[mt][nt][2], acc[mt][nt][3]);
        }
    }
}

// ---------------------------------------------------------------------------
// RoPE table: angle in fp64 once per (t, freq) pair.
// ---------------------------------------------------------------------------
__global__ __launch_bounds__(256) void rope_table() {
    int idx = blockIdx.x * 256 + threadIdx.x;
    if (idx >= Tt * 64) return;
    int t = idx >> 6, i = idx & 63;
    double ang = (double)t * exp(-0.21586735246819178 * (double)i); // ln(1e6)/64
    double s, c;
    sincos(ang, &s, &c);
    g_sin[idx] = (float)s;
    g_cos[idx] = (float)c;
}

// ---------------------------------------------------------------------------
// Fused RMSNorm + RoPE, in place on a (rows, heads, HD) buffer.
// One block (128 threads) per (row, head). pos = t (cur_ind=0, no left pad).
// ---------------------------------------------------------------------------
__global__ __launch_bounds__(128) void rms_rope(float* __restrict__ buf,
                                                const float* __restrict__ w,
                                                int heads) {
    const int idx = blockIdx.x;
    const int t = (idx / heads) % Tt;
    float* p = buf + (size_t)idx * HD;
    const int h = threadIdx.x;

    float x = p[h];
    float ss = x * x;
#pragma unroll
    for (int off = 16; off; off >>= 1) ss += __shfl_xor_sync(0xffffffffu, ss, off);
    __shared__ float red[4];
    __shared__ float sy[HD];
    if ((h & 31) == 0) red[h >> 5] = ss;
    __syncthreads();
    float tot = red[0] + red[1] + red[2] + red[3];
    float rinv = rsqrtf(tot * (1.0f / (float)HD) + 1e-6f);
    float y = w[h] * x * rinv;
    sy[h] = y;
    __syncthreads();

    int i = h & 63;
    float s = g_sin[t * 64 + i];
    float c = g_cos[t * 64 + i];
    float out;
    if (h < 64) out = y * c - sy[h + 64] * s;
    else        out = y * c + sy[h - 64] * s;
    p[h] = out;
}

// ---------------------------------------------------------------------------
// Flash attention, fp32, causal. Tile 64 (M) x 64 (N), H=128.
// Grid: (T/64, NQ, B). 256 threads.
// ---------------------------------------------------------------------------
#define KSTR 132
__global__ __launch_bounds__(256) void flash_attn(const float* __restrict__ Q,
                                                  const float* __restrict__ Kc,
                                                  const float* __restrict__ Vc,
                                                  float* __restrict__ O) {
    extern __shared__ float sm[];
    float* sQ = sm;                   // 64 x KSTR
    float* sK = sm + 64 * KSTR;       // 64 x KSTR
    float* sV = sm + 2 * 64 * KSTR;   // 64 x HD
    float* sP = sV + 64 * HD;         // 64 x 64

    const int tid = threadIdx.x;
    const int b = blockIdx.z, n = blockIdx.y;
    const int qt = blockIdx.x << 6;
    const int kh = n >> 1; // G = NQ/NK = 2

    {
        const float* Qb = Q + (((size_t)(b * Tt + qt)) * NQ + n) * HD;
#pragma unroll
        for (int u = 0; u < 8; u++) {
            int f = tid + (u << 8);
            int r = f >> 5, c = (f & 31) << 2;
            *(float4*)&sQ[r * KSTR + c] = *(const float4*)(Qb + (size_t)r * (NQ * HD) + c);
        }
    }

    const int r0 = (tid >> 4) << 2;
    const int c1 = tid & 15;
    const int oc = c1 << 3;

    float mprev[4], lsum[4], oacc[4][8];
#pragma unroll
    for (int i = 0; i < 4; i++) {
        mprev[i] = -1e30f;
        lsum[i] = 0.f;
#pragma unroll
        for (int j = 0; j < 8; j++) oacc[i][j] = 0.f;
    }

    const float scale = 0.08838834764831845f; // 1/sqrt(128)
    const int ntile = (qt >> 6) + 1;

    for (int st = 0; st < ntile; st++) {
        const int s0 = st << 6;
        __syncthreads();
        {
            const float* Kb = Kc + (((size_t)(b * Tt + s0)) * NK + kh) * HD;
            const float* Vb = Vc + (((size_t)(b * Tt + s0)) * NK + kh) * HD;
#pragma unroll
            for (int u = 0; u < 8; u++) {
                int f = tid + (u << 8);
                int r = f >> 5, c = (f & 31) << 2;
                *(float4*)&sK[r * KSTR + c] = *(const float4*)(Kb + (size_t)r * (NK * HD) + c);
                *(float4*)&sV[r * HD + c]  = *(const float4*)(Vb + (size_t)r * (NK * HD) + c);
            }
        }
        __syncthreads();

        float sacc[4][4];
#pragma unroll
        for (int i = 0; i < 4; i++)
#pragma unroll
            for (int j = 0; j < 4; j++) sacc[i][j] = 0.f;

#pragma unroll 4
        for (int k = 0; k < HD; k += 4) {
            float4 qv[4], kv[4];
#pragma unroll
            for (int i = 0; i < 4; i++) qv[i] = *(const float4*)&sQ[(r0 + i) * KSTR + k];
#pragma unroll
            for (int j = 0; j < 4; j++) kv[j] = *(const float4*)&sK[(c1 + (j << 4)) * KSTR + k];
#pragma unroll
            for (int i = 0; i < 4; i++)
#pragma unroll
                for (int j = 0; j < 4; j++) {
                    sacc[i][j] = fmaf(qv[i].x, kv[j].x, sacc[i][j]);
                    sacc[i][j] = fmaf(qv[i].y, kv[j].y, sacc[i][j]);
                    sacc[i][j] = fmaf(qv[i].z, kv[j].z, sacc[i][j]);
                    sacc[i][j] = fmaf(qv[i].w, kv[j].w, sacc[i][j]);
                }
        }

        const bool diag = (s0 == qt);
#pragma unroll
        for (int i = 0; i < 4; i++) {
            const int qrow = qt + r0 + i;
            float mx = -1e30f;
#pragma unroll
            for (int j = 0; j < 4; j++) {
                float v = sacc[i][j] * scale;
                if (diag && (s0 + c1 + (j << 4)) > qrow) v = -1e30f;
                sacc[i][j] = v;
                mx = fmaxf(mx, v);
            }
#pragma unroll
            for (int off = 1; off < 16; off <<= 1)
                mx = fmaxf(mx, __shfl_xor_sync(0xffffffffu, mx, off));
            float mnew = fmaxf(mprev[i], mx);
            float alpha = __expf(mprev[i] - mnew);
            mprev[i] = mnew;
            float psum = 0.f;
#pragma unroll
            for (int j = 0; j < 4; j++) {
                float pv = __expf(sacc[i][j] - mnew);
                sP[(r0 + i) * 64 + c1 + (j << 4)] = pv;
                psum += pv;
            }
#pragma unroll
            for (int off = 1; off < 16; off <<= 1)
                psum += __shfl_xor_sync(0xffffffffu, psum, off);
            lsum[i] = lsum[i] * alpha + psum;
#pragma unroll
            for (int j = 0; j < 8; j++) oacc[i][j] *= alpha;
        }
        __syncwarp();

#pragma unroll 2
        for (int s = 0; s < 64; s++) {
            float4 v0 = *(const float4*)&sV[s * HD + oc];
            float4 v1 = *(const float4*)&sV[s * HD + oc + 4];
#pragma unroll
            for (int i = 0; i < 4; i++) {
                float pv = sP[(r0 + i) * 64 + s];
                oacc[i][0] = fmaf(pv, v0.x, oacc[i][0]);
                oacc[i][1] = fmaf(pv, v0.y, oacc[i][1]);
                oacc[i][2] = fmaf(pv, v0.z, oacc[i][2]);
                oacc[i][3] = fmaf(pv, v0.w, oacc[i][3]);
                oacc[i][4] = fmaf(pv, v1.x, oacc[i][4]);
                oacc[i][5] = fmaf(pv, v1.y, oacc[i][5]);
                oacc[i][6] = fmaf(pv, v1.z, oacc[i][6]);
                oacc[i][7] = fmaf(pv, v1.w, oacc[i][7]);
            }
        }
    }

#pragma unroll
    for (int i = 0; i < 4; i++) {
        float inv = 1.0f / lsum[i];
        float* Ob = O + (((size_t)(b * Tt + qt + r0 + i)) * NQ + n) * HD + oc;
        *(float4*)Ob = make_float4(oacc[i][0] * inv, oacc[i][1] * inv,
                                   oacc[i][2] * inv, oacc[i][3] * inv);
        *(float4*)(Ob + 4) = make_float4(oacc[i][4] * inv, oacc[i][5] * inv,
                                         oacc[i][6] * inv, oacc[i][7] * inv);
    }
}

// ---------------------------------------------------------------------------
// Launch
// ---------------------------------------------------------------------------
extern "C" void kernel_launch(void* const* d_in, const int* in_sizes, int n_in,
                              void* d_out, int out_size) {
    (void)in_sizes; (void)n_in; (void)out_size;
    const float* x   = (const float*)d_in[0];
    const float* qw  = (const float*)d_in[1];
    const float* kw  = (const float*)d_in[2];
    const float* vw  = (const float*)d_in[3];
    const float* ow  = (const float*)d_in[4];
    const float* qnw = (const float*)d_in[5];
    const float* knw = (const float*)d_in[6];
    float* out = (float*)d_out;

    float *gq, *gk, *gv, *go;
    cudaGetSymbolAddress((void**)&gq, g_q);
    cudaGetSymbolAddress((void**)&gk, g_k);
    cudaGetSymbolAddress((void**)&gv, g_v);
    cudaGetSymbolAddress((void**)&go, g_o);

    const int M = Bb * Tt; // 4096

    // RoPE table (tiny)
    rope_table<<<(Tt * 64 + 255) / 256, 256>>>();

    // QKV projections (tf32 tensor cores)
    gemm_tf32<<<dim3((NQ * HD) / 128, M / 128), 256>>>(x, qw, gq, M, NQ * HD, Dd);
    gemm_tf32<<<dim3((NK * HD) / 128, M / 128), 256>>>(x, kw, gk, M, NK * HD, Dd);
    gemm_tf32<<<dim3((NK * HD) / 128, M / 128), 256>>>(x, vw, gv, M, NK * HD, Dd);

    // RMSNorm + RoPE (in place)
    rms_rope<<<M * NQ, 128>>>(gq, qnw, NQ);
    rms_rope<<<M * NK, 128>>>(gk, knw, NK);

    // Flash attention
    size_t smem = (size_t)(2 * 64 * KSTR + 64 * HD + 64 * 64) * sizeof(float); // 116736 B
    cudaFuncSetAttribute(flash_attn, cudaFuncAttributeMaxDynamicSharedMemorySize, (int)smem);
    flash_attn<<<dim3(Tt / 64, NQ, Bb), 256, smem>>>(gq, gk, gv, go);

    // Output projection (tf32 tensor cores)
    gemm_tf32<<<dim3(Dd / 128, M / 128), 256>>>(go, ow, out, M, Dd, NQ * HD);
}